// round 16
// baseline (speedup 1.0000x reference)
#include <cuda_runtime.h>
#include <cuda_fp16.h>

// CustomAttention: out[b,n] = b0 * sum_m tanh(a0*x[b,n]*x[b,m]) * x[b,m]
// B=16, N=4096. Symmetric 256x256 tiling, MUFU.f16x2 roofline (~34us).
// R16: PERSISTENT blocks + work stealing. Static 1.84-wave schedule wasted
// ~6us in wave-2 quantization + spread; now 1184 resident blocks pull
// (batch,pair) units from a global queue (diagonal/light units last as
// tail filler). Int fixed-point RED accumulation (R15) keeps the output
// bit-deterministic under any steal order. Queue self-resets for replay.

#define NBATCH 16
#define NDIM   4096
#define TILE   256
#define NTILE  (NDIM / TILE)              // 16
#define NOFF   (NTILE * (NTILE - 1) / 2)  // 120
#define NUNITS (NBATCH * (NOFF + NTILE))  // 2176 work units
#define NOFFU  (NBATCH * NOFF)            // 1920 off-diag units (first)
#define GRID   1184                       // 148 SMs x 8 blocks
#define BT     256
#define FSCALE 65536.0f
#define INV_FSCALE (1.0f / 65536.0f)

__device__ int g_accum[NBATCH][NDIM];     // 256 KB, zero-init, self-resetting
__device__ int g_arrive[NBATCH][NTILE];   // tile arrival counters
__device__ int g_work;                    // work-steal cursor
__device__ int g_done;                    // block-done counter (for reset)

__device__ __forceinline__ __half2 tanh2(__half2 v) {
    unsigned u = *reinterpret_cast<unsigned*>(&v);
    unsigned r;
    asm("tanh.approx.f16x2 %0, %1;" : "=r"(r) : "r"(u));
    return *reinterpret_cast<__half2*>(&r);
}
__device__ __forceinline__ unsigned h2u(__half2 v) { return *reinterpret_cast<unsigned*>(&v); }
__device__ __forceinline__ __half2 u2h(unsigned v) { return *reinterpret_cast<__half2*>(&v); }

__device__ __forceinline__ int arrive_acqrel(int* ctr) {
    int old;
    asm volatile("atom.add.acq_rel.gpu.global.s32 %0, [%1], 1;"
                 : "=r"(old) : "l"(ctr) : "memory");
    return old;
}

__device__ __forceinline__ void finalize_tile(int batch, int R, float b0,
                                              float* __restrict__ out, int tid)
{
    const int n = R * TILE + tid;
    int v = __ldcg(&g_accum[batch][n]);
    out[batch * NDIM + n] = b0 * ((float)v * INV_FSCALE);
    g_accum[batch][n] = 0;                 // reset for next replay
}

__global__ __launch_bounds__(BT, 8)
void sym_tile_kernel(const float* __restrict__ x,
                     const float* __restrict__ a,
                     const float* __restrict__ bco,
                     float* __restrict__ out)
{
    __shared__ __half2 xhJd[4][64];            // replicated col tile, 2 KB
    __shared__ float2  colred[8][TILE / 2];    // 8 KB
    __shared__ int     s_unit;
    __shared__ int     s_old[2];

    const int tid = threadIdx.x;
    const int w   = tid >> 5;
    const int L   = tid & 31;
    const float b0 = bco[0];

    while (true) {
        if (tid == 0) s_unit = atomicAdd(&g_work, 1);
        __syncthreads();
        const int u = s_unit;
        if (u >= NUNITS) break;

        // Decode: units 0..1919 off-diag (heavy, first); 1920.. diag (light, last)
        int batch, I, J;
        if (u < NOFFU) {
            batch = u / NOFF;
            int q = u - batch * NOFF, i = 0;
            while (true) { int cnt = NTILE - 1 - i; if (q < cnt) break; q -= cnt; i++; }
            I = i; J = i + 1 + q;
        } else {
            int v = u - NOFFU;
            batch = v >> 4;
            I = J = v & (NTILE - 1);
        }

        const float* __restrict__ xb = x + batch * NDIM;

        // Fill replicated col tile: 4 rb x 64 entries
        {
            const int rb = tid >> 6;
            const int j  = tid & 63;
            const int pr = rb * 32 + (j & 31);
            float2 v = reinterpret_cast<const float2*>(xb + J * TILE)[pr];
            xhJd[rb][j] = __floats2half2_rn(v.x, v.y);
        }

        const float xn = xb[I * TILE + tid];
        const __half2 ch  = __float2half2_rn(a[0] * xn);
        const __half2 xi2 = __float2half2_rn(xn);
        __syncthreads();

        float row_f = 0.f;

        if (I == J) {
            #pragma unroll 1
            for (int rb = 0; rb < 4; ++rb) {
                __half2 racc = __float2half2_rn(0.f);
                #pragma unroll
                for (int k = 0; k < 32; ++k) {
                    __half2 h = xhJd[rb][k];
                    racc = __hfma2(tanh2(__hmul2(ch, h)), h, racc);
                }
                float2 f = __half22float2(racc);
                row_f += f.x + f.y;
            }
            atomicAdd(&g_accum[batch][I * TILE + tid],
                      __float2int_rn(row_f * FSCALE));
            __syncthreads();                   // REDs issued before arrival
            if (tid == 0)  s_old[0] = arrive_acqrel(&g_arrive[batch][I]);
            if (tid == 32) s_old[1] = -1;
        } else {
            #pragma unroll 1
            for (int rb = 0; rb < 4; ++rb) {
                __half2 racc = __float2half2_rn(0.f);
                __half2 cacc = __float2half2_rn(0.f);
                #pragma unroll
                for (int k = 0; k < 32; ++k) {
                    __half2 h = xhJd[rb][L + k];         // affine LDS
                    __half2 t = tanh2(__hmul2(ch, h));
                    racc = __hfma2(t, h, racc);          // rows of I
                    unsigned v2 = h2u(__hmul2(t, xi2));  // t*x_row -> rows of J
                    unsigned rv = __shfl_sync(0xffffffffu, v2, L + 32 - k);
                    cacc = __hadd2(cacc, u2h(rv));
                }
                float2 f = __half22float2(racc);
                row_f += f.x + f.y;
                colred[w][rb * 32 + L] = __half22float2(cacc);
            }
            __syncthreads();

            float s = 0.f;
            #pragma unroll
            for (int w2 = 0; w2 < 8; ++w2) {
                float2 f = colred[w2][tid >> 1];
                s += (tid & 1) ? f.y : f.x;
            }
            atomicAdd(&g_accum[batch][I * TILE + tid],
                      __float2int_rn(row_f * FSCALE));
            atomicAdd(&g_accum[batch][J * TILE + tid],
                      __float2int_rn(s * FSCALE));
            __syncthreads();                   // REDs issued before arrival
            if (tid == 0)  s_old[0] = arrive_acqrel(&g_arrive[batch][I]);
            if (tid == 32) s_old[1] = arrive_acqrel(&g_arrive[batch][J]);
        }
        __syncthreads();

        // Election: 16th arriver finalizes that tile (1 load per output).
        if (s_old[0] == NTILE - 1) {
            finalize_tile(batch, I, b0, out, tid);
            if (tid == 0) g_arrive[batch][I] = 0;
        }
        if (s_old[1] == NTILE - 1) {
            finalize_tile(batch, J, b0, out, tid);
            if (tid == 32) g_arrive[batch][J] = 0;
        }
        __syncthreads();                       // smem reuse next iteration
    }

    // Queue self-reset: last block to finish rewinds the cursor.
    if (tid == 0) {
        int d = atomicAdd(&g_done, 1);
        if (d == GRID - 1) { g_work = 0; g_done = 0; }
    }
}

extern "C" void kernel_launch(void* const* d_in, const int* in_sizes, int n_in,
                              void* d_out, int out_size)
{
    const float* x = (const float*)d_in[0];
    const float* a = (const float*)d_in[1];
    const float* b = (const float*)d_in[2];
    float* out = (float*)d_out;

    sym_tile_kernel<<<GRID, BT>>>(x, a, b, out);   // 1184 persistent blocks
}